// round 11
// baseline (speedup 1.0000x reference)
#include <cuda_runtime.h>
#include <cstdint>

// 9-DoF alignment, one WARP per batch, TMA-bulk (cp.async.bulk / UBLKCP)
// staging with per-warp mbarrier ring. Replaces per-thread LDGSTS streams
// with 1536B hardware bulk bursts for DRAM-friendlier request streams.
//
// Per warp: 3-slot smem ring (3072B data/slot: 1536B x + 1536B y) + 3
// mbarriers. Chunk c+2 is issued before waiting on chunk c (2 in flight).
// Readback: scalar LDS.32, bank-conflict-free (gcd(3,32)=1).
// No __syncthreads; mbarrier wait + __syncwarp only.

#define SLOT_BYTES   3072
#define NSLOT        3
#define WARP_DATA    (NSLOT * SLOT_BYTES)       // 9216B
#define WARP_MBAR    64                          // 3 mbarriers (8B each) padded
#define WARP_SMEM    (WARP_DATA + WARP_MBAR)     // 9280B
#define CTA_SMEM     (8 * WARP_SMEM)             // 74240B

__device__ __forceinline__ void mbar_init(uint32_t mbar, uint32_t count) {
    asm volatile("mbarrier.init.shared::cta.b64 [%0], %1;"
                 :: "r"(mbar), "r"(count) : "memory");
}
__device__ __forceinline__ void mbar_expect_tx(uint32_t mbar, uint32_t bytes) {
    asm volatile("mbarrier.arrive.expect_tx.shared::cta.b64 _, [%0], %1;"
                 :: "r"(mbar), "r"(bytes) : "memory");
}
__device__ __forceinline__ void bulk_ld(uint32_t dst, const void* src,
                                        uint32_t bytes, uint32_t mbar) {
    asm volatile("cp.async.bulk.shared::cta.global.mbarrier::complete_tx::bytes"
                 " [%0], [%1], %2, [%3];"
                 :: "r"(dst), "l"(src), "r"(bytes), "r"(mbar) : "memory");
}
__device__ __forceinline__ void mbar_wait(uint32_t mbar, uint32_t parity) {
    uint32_t done;
    asm volatile(
        "{\n\t.reg .pred p;\n\t"
        "mbarrier.try_wait.parity.acquire.cta.shared::cta.b64 p, [%1], %2;\n\t"
        "selp.b32 %0, 1, 0, p;\n\t}"
        : "=r"(done) : "r"(mbar), "r"(parity) : "memory");
    if (!done) {
        asm volatile(
            "{\n\t.reg .pred P1;\n\t"
            "WL_%=:\n\t"
            "mbarrier.try_wait.parity.acquire.cta.shared::cta.b64 P1, [%0], %1, 0x989680;\n\t"
            "@P1 bra.uni WD_%=;\n\t"
            "bra.uni WL_%=;\n\t"
            "WD_%=:\n\t}"
            :: "r"(mbar), "r"(parity) : "memory");
    }
}

__global__ __launch_bounds__(256, 3)
void align9dof_kernel(const float* __restrict__ x,
                      const float* __restrict__ mu_x,
                      const float* __restrict__ y,
                      const float* __restrict__ mu_y,
                      float* __restrict__ out,
                      int B)
{
    extern __shared__ char smem_dyn[];

    const int warp = threadIdx.x >> 5;
    const int lane = threadIdx.x & 31;
    const int b    = blockIdx.x * 8 + warp;
    if (b >= B) return;

    char* wbase = smem_dyn + warp * WARP_SMEM;
    const uint32_t sbase = (uint32_t)__cvta_generic_to_shared(wbase);
    const uint32_t mbase = sbase + WARP_DATA;

    // Init this warp's 3 mbarriers (single lane), make visible to async proxy
    if (lane == 0) {
#pragma unroll
        for (int s = 0; s < NSLOT; s++) mbar_init(mbase + s * 8, 1);
        asm volatile("fence.proxy.async.shared::cta;" ::: "memory");
    }
    __syncwarp();

    // Per-batch means (uniform broadcast loads)
    const float mx0 = mu_x[b * 3 + 0];
    const float mx1 = mu_x[b * 3 + 1];
    const float mx2 = mu_x[b * 3 + 2];
    const float my0 = mu_y[b * 3 + 0];
    const float my1 = mu_y[b * 3 + 1];
    const float my2 = mu_y[b * 3 + 2];

    const char* __restrict__ gx = (const char*)(x + (size_t)b * 3072);
    const char* __restrict__ gy = (const char*)(y + (size_t)b * 3072);

    // Issue chunk c: 1536B of x + 1536B of y into slot c%3 (lane 0 only)
    auto issue_chunk = [&](int c) {
        if (lane == 0) {
            const uint32_t mb  = mbase + (c % 3) * 8;
            const uint32_t dst = sbase + (c % 3) * SLOT_BYTES;
            mbar_expect_tx(mb, SLOT_BYTES);
            bulk_ld(dst,        gx + c * 1536, 1536, mb);
            bulk_ld(dst + 1536, gy + c * 1536, 1536, mb);
        }
    };

    // Prologue: chunks 0 and 1 in flight
    issue_chunk(0);
    issue_chunk(1);

    float v[11];  // c00..c22, sxx, syy
#pragma unroll
    for (int i = 0; i < 11; i++) v[i] = 0.0f;

#pragma unroll
    for (int c = 0; c < 8; c++) {
        // Keep 2 chunks ahead (slot c+2 was consumed at c-1, safe to refill)
        if (c + 2 < 8) issue_chunk(c + 2);

        // Wait for chunk c (use number c/3, parity alternates per reuse)
        mbar_wait(mbase + (c % 3) * 8, (c / 3) & 1);

        const float* fx = (const float*)(wbase + (c % 3) * SLOT_BYTES);
        const float* fy = fx + 384;  // +1536B

#pragma unroll
        for (int g = 0; g < 4; g++) {
            const int p = g * 32 + lane;
            const float u0 = fx[3 * p + 0] - mx0;
            const float u1 = fx[3 * p + 1] - mx1;
            const float u2 = fx[3 * p + 2] - mx2;
            const float w0 = fy[3 * p + 0] - my0;
            const float w1 = fy[3 * p + 1] - my1;
            const float w2 = fy[3 * p + 2] - my2;
            v[0] = fmaf(u0, w0, v[0]); v[1] = fmaf(u0, w1, v[1]); v[2] = fmaf(u0, w2, v[2]);
            v[3] = fmaf(u1, w0, v[3]); v[4] = fmaf(u1, w1, v[4]); v[5] = fmaf(u1, w2, v[5]);
            v[6] = fmaf(u2, w0, v[6]); v[7] = fmaf(u2, w1, v[7]); v[8] = fmaf(u2, w2, v[8]);
            v[9]  = fmaf(u0, u0, fmaf(u1, u1, fmaf(u2, u2, v[9])));
            v[10] = fmaf(w0, w0, fmaf(w1, w1, fmaf(w2, w2, v[10])));
        }
        __syncwarp();  // all lanes done reading slot before lane 0 refills it
    }

    // Warp butterfly reduction: all lanes end with the full batch sums
#pragma unroll
    for (int off = 16; off > 0; off >>= 1) {
#pragma unroll
        for (int i = 0; i < 11; i++)
            v[i] += __shfl_xor_sync(0xFFFFFFFFu, v[i], off);
    }

    // ---- Polar factor via determinant-scaled Newton (all lanes, redundant) ----
    float fro2 = 0.0f;
#pragma unroll
    for (int i = 0; i < 9; i++) fro2 = fmaf(v[i], v[i], fro2);
    const float invf = rsqrtf(fmaxf(fro2, 1e-30f));

    float X[9];
#pragma unroll
    for (int i = 0; i < 9; i++) X[i] = v[i] * invf;

#pragma unroll
    for (int it = 0; it < 8; it++) {
        float C[9];  // cofactors: X^{-T} = C / det
        C[0] = X[4] * X[8] - X[5] * X[7];
        C[1] = X[5] * X[6] - X[3] * X[8];
        C[2] = X[3] * X[7] - X[4] * X[6];
        C[3] = X[2] * X[7] - X[1] * X[8];
        C[4] = X[0] * X[8] - X[2] * X[6];
        C[5] = X[1] * X[6] - X[0] * X[7];
        C[6] = X[1] * X[5] - X[2] * X[4];
        C[7] = X[2] * X[3] - X[0] * X[5];
        C[8] = X[0] * X[4] - X[1] * X[3];
        float det = X[0] * C[0] + X[1] * C[1] + X[2] * C[2];
        float ad  = fmaxf(fabsf(det), 1e-30f);
        float eta = rcbrtf(ad);            // |det|^{-1/3}
        float k1  = 0.5f * eta;
        float k2  = 0.5f / (eta * det);    // keeps det's sign
#pragma unroll
        for (int i = 0; i < 9; i++) X[i] = k1 * X[i] + k2 * C[i];
    }

    // t = mu_y - R mu_x
    const float t0 = my0 - (X[0] * mx0 + X[1] * mx1 + X[2] * mx2);
    const float t1 = my1 - (X[3] * mx0 + X[4] * mx1 + X[5] * mx2);
    const float t2 = my2 - (X[6] * mx0 + X[7] * mx1 + X[8] * mx2);

    const float sf = sqrtf(v[10]) / (sqrtf(v[9]) + 1e-6f);

    // ---- Coalesced predicated stores ----
    if (lane < 9) {
        float r = (lane == 0) ? X[0] :
                  (lane == 1) ? X[1] :
                  (lane == 2) ? X[2] :
                  (lane == 3) ? X[3] :
                  (lane == 4) ? X[4] :
                  (lane == 5) ? X[5] :
                  (lane == 6) ? X[6] :
                  (lane == 7) ? X[7] : X[8];
        out[(size_t)b * 9 + lane] = r;
    }
    if (lane < 3) {
        float tv = (lane == 0) ? t0 : (lane == 1) ? t1 : t2;
        out[(size_t)B * 9 + (size_t)b * 3 + lane] = tv;
    }
    if (lane == 0) {
        out[(size_t)B * 12 + b] = sf;
    }
}

extern "C" void kernel_launch(void* const* d_in, const int* in_sizes, int n_in,
                              void* d_out, int out_size)
{
    const float* x    = (const float*)d_in[0];
    const float* mu_x = (const float*)d_in[1];
    const float* y    = (const float*)d_in[2];
    const float* mu_y = (const float*)d_in[3];
    float* out        = (float*)d_out;

    const int B = in_sizes[1] / 3;  // mu_x is [B,3]

    cudaFuncSetAttribute(align9dof_kernel,
                         cudaFuncAttributeMaxDynamicSharedMemorySize, CTA_SMEM);

    align9dof_kernel<<<(B + 7) / 8, 256, CTA_SMEM>>>(x, mu_x, y, mu_y, out, B);
}

// round 12
// speedup vs baseline: 1.3605x; 1.3605x over previous
#include <cuda_runtime.h>
#include <cstdint>

// 9-DoF alignment. 2048 persistent warps (256 CTAs x 8), each owning exactly
// 4 contiguous batches: perfect balance, single wave, no ragged tail.
// cp.async staging, 4-slot smem ring per warp, 3 chunks in flight, pipeline
// continuous across the warp's 4 batches (epilogue overlapped with loads).
//
// Chunk = 128 points (1536B x + 1536B y), 8 chunks/batch, 32 chunks/warp.
// Readback: scalar LDS.32, bank-conflict-free (gcd(3,32)=1).
// No __syncthreads; cp.async.wait_group + __syncwarp only.

#define SLOT_BYTES   3072
#define NSLOT        4
#define WARP_SMEM    (NSLOT * SLOT_BYTES)   // 12288B ring per warp
#define CTA_SMEM     (8 * WARP_SMEM)        // 98304B per CTA (8 warps)
#define BATCHES_PER_WARP 4

__device__ __forceinline__ void cp_async16(uint32_t saddr, const void* gaddr) {
    asm volatile("cp.async.cg.shared.global [%0], [%1], 16;\n"
                 :: "r"(saddr), "l"(gaddr));
}
__device__ __forceinline__ void cp_commit() {
    asm volatile("cp.async.commit_group;\n");
}
template <int N>
__device__ __forceinline__ void cp_wait() {
    asm volatile("cp.async.wait_group %0;\n" :: "n"(N));
}

__global__ __launch_bounds__(256, 2)
void align9dof_kernel(const float* __restrict__ x,
                      const float* __restrict__ mu_x,
                      const float* __restrict__ y,
                      const float* __restrict__ mu_y,
                      float* __restrict__ out,
                      int B)
{
    extern __shared__ char smem_dyn[];

    const int warp = threadIdx.x >> 5;
    const int lane = threadIdx.x & 31;
    const int gw   = blockIdx.x * 8 + warp;      // global warp id
    const int b0   = gw * BATCHES_PER_WARP;      // first of 4 contiguous batches
    if (b0 >= B) return;

    int nb = B - b0;
    if (nb > BATCHES_PER_WARP) nb = BATCHES_PER_WARP;
    const int qtot = nb * 8;                      // chunks in this warp's stream

    char* wbase = smem_dyn + warp * WARP_SMEM;
    const uint32_t sbase = (uint32_t)__cvta_generic_to_shared(wbase);

    // Issue chunk q of the stream: batch b0 + (q>>3), chunk (q&7)
    auto issue_chunk = [&](int q) {
        const size_t bq = (size_t)b0 + (q >> 3);
        const char* gx = (const char*)(x + bq * 3072) + (q & 7) * 1536 + lane * 16;
        const char* gy = (const char*)(y + bq * 3072) + (q & 7) * 1536 + lane * 16;
        const uint32_t s = sbase + (q & (NSLOT - 1)) * SLOT_BYTES + lane * 16;
#pragma unroll
        for (int k = 0; k < 3; k++) {
            cp_async16(s + k * 512,        gx + k * 512);
            cp_async16(s + 1536 + k * 512, gy + k * 512);
        }
        cp_commit();
    };

    // Prologue: three chunks in flight (qtot >= 8 always)
    issue_chunk(0);
    issue_chunk(1);
    issue_chunk(2);

    float mx0 = 0.f, mx1 = 0.f, mx2 = 0.f, my0 = 0.f, my1 = 0.f, my2 = 0.f;

    float v[11];  // c00..c22, sxx, syy
#pragma unroll
    for (int i = 0; i < 11; i++) v[i] = 0.0f;

    for (int q = 0; q < qtot; q++) {
        // Keep the stream 3 chunks ahead (crosses batch boundaries)
        if (q + 3 < qtot) issue_chunk(q + 3);

        // Wait until chunk q is complete (groups complete in order)
        const int younger = qtot - 1 - q < 3 ? qtot - 1 - q : 3;
        if (younger == 3)      cp_wait<3>();
        else if (younger == 2) cp_wait<2>();
        else if (younger == 1) cp_wait<1>();
        else                   cp_wait<0>();
        __syncwarp();

        const int bcur = b0 + (q >> 3);
        if ((q & 7) == 0) {
            mx0 = mu_x[bcur * 3 + 0];
            mx1 = mu_x[bcur * 3 + 1];
            mx2 = mu_x[bcur * 3 + 2];
            my0 = mu_y[bcur * 3 + 0];
            my1 = mu_y[bcur * 3 + 1];
            my2 = mu_y[bcur * 3 + 2];
        }

        const float* fx = (const float*)(wbase + (q & (NSLOT - 1)) * SLOT_BYTES);
        const float* fy = fx + 384;  // +1536B

#pragma unroll
        for (int g = 0; g < 4; g++) {
            const int p = g * 32 + lane;
            const float u0 = fx[3 * p + 0] - mx0;
            const float u1 = fx[3 * p + 1] - mx1;
            const float u2 = fx[3 * p + 2] - mx2;
            const float w0 = fy[3 * p + 0] - my0;
            const float w1 = fy[3 * p + 1] - my1;
            const float w2 = fy[3 * p + 2] - my2;
            v[0] = fmaf(u0, w0, v[0]); v[1] = fmaf(u0, w1, v[1]); v[2] = fmaf(u0, w2, v[2]);
            v[3] = fmaf(u1, w0, v[3]); v[4] = fmaf(u1, w1, v[4]); v[5] = fmaf(u1, w2, v[5]);
            v[6] = fmaf(u2, w0, v[6]); v[7] = fmaf(u2, w1, v[7]); v[8] = fmaf(u2, w2, v[8]);
            v[9]  = fmaf(u0, u0, fmaf(u1, u1, fmaf(u2, u2, v[9])));
            v[10] = fmaf(w0, w0, fmaf(w1, w1, fmaf(w2, w2, v[10])));
        }
        __syncwarp();  // all lanes done reading slot before refill

        if ((q & 7) == 7) {
            // ---- Batch epilogue (next batch's loads already in flight) ----
#pragma unroll
            for (int off = 16; off > 0; off >>= 1) {
#pragma unroll
                for (int i = 0; i < 11; i++)
                    v[i] += __shfl_xor_sync(0xFFFFFFFFu, v[i], off);
            }

            float fro2 = 0.0f;
#pragma unroll
            for (int i = 0; i < 9; i++) fro2 = fmaf(v[i], v[i], fro2);
            const float invf = rsqrtf(fmaxf(fro2, 1e-30f));

            float X[9];
#pragma unroll
            for (int i = 0; i < 9; i++) X[i] = v[i] * invf;

#pragma unroll
            for (int it = 0; it < 8; it++) {
                float C[9];  // cofactors: X^{-T} = C / det
                C[0] = X[4] * X[8] - X[5] * X[7];
                C[1] = X[5] * X[6] - X[3] * X[8];
                C[2] = X[3] * X[7] - X[4] * X[6];
                C[3] = X[2] * X[7] - X[1] * X[8];
                C[4] = X[0] * X[8] - X[2] * X[6];
                C[5] = X[1] * X[6] - X[0] * X[7];
                C[6] = X[1] * X[5] - X[2] * X[4];
                C[7] = X[2] * X[3] - X[0] * X[5];
                C[8] = X[0] * X[4] - X[1] * X[3];
                float det = X[0] * C[0] + X[1] * C[1] + X[2] * C[2];
                float ad  = fmaxf(fabsf(det), 1e-30f);
                float eta = rcbrtf(ad);            // |det|^{-1/3}
                float k1  = 0.5f * eta;
                float k2  = 0.5f / (eta * det);    // keeps det's sign
#pragma unroll
                for (int i = 0; i < 9; i++) X[i] = k1 * X[i] + k2 * C[i];
            }

            const float t0 = my0 - (X[0] * mx0 + X[1] * mx1 + X[2] * mx2);
            const float t1 = my1 - (X[3] * mx0 + X[4] * mx1 + X[5] * mx2);
            const float t2 = my2 - (X[6] * mx0 + X[7] * mx1 + X[8] * mx2);
            const float sf = sqrtf(v[10]) / (sqrtf(v[9]) + 1e-6f);

            if (lane < 9) {
                float r = (lane == 0) ? X[0] :
                          (lane == 1) ? X[1] :
                          (lane == 2) ? X[2] :
                          (lane == 3) ? X[3] :
                          (lane == 4) ? X[4] :
                          (lane == 5) ? X[5] :
                          (lane == 6) ? X[6] :
                          (lane == 7) ? X[7] : X[8];
                out[(size_t)bcur * 9 + lane] = r;
            }
            if (lane < 3) {
                float tv = (lane == 0) ? t0 : (lane == 1) ? t1 : t2;
                out[(size_t)B * 9 + (size_t)bcur * 3 + lane] = tv;
            }
            if (lane == 0) {
                out[(size_t)B * 12 + bcur] = sf;
            }

#pragma unroll
            for (int i = 0; i < 11; i++) v[i] = 0.0f;
        }
    }
}

extern "C" void kernel_launch(void* const* d_in, const int* in_sizes, int n_in,
                              void* d_out, int out_size)
{
    const float* x    = (const float*)d_in[0];
    const float* mu_x = (const float*)d_in[1];
    const float* y    = (const float*)d_in[2];
    const float* mu_y = (const float*)d_in[3];
    float* out        = (float*)d_out;

    const int B = in_sizes[1] / 3;  // mu_x is [B,3]

    cudaFuncSetAttribute(align9dof_kernel,
                         cudaFuncAttributeMaxDynamicSharedMemorySize, CTA_SMEM);

    // 4 batches per warp, 8 warps per CTA -> one CTA per 32 batches.
    const int grid = (B + 31) / 32;   // 256 CTAs for B=8192: single wave

    align9dof_kernel<<<grid, 256, CTA_SMEM>>>(x, mu_x, y, mu_y, out, B);
}

// round 13
// speedup vs baseline: 1.3682x; 1.0057x over previous
#include <cuda_runtime.h>
#include <cstdint>

// 9-DoF alignment, persistent warps + cp.async staging (R9 structure) with a
// slimmed consume loop: LDS.128 readback + packed f32x2 arithmetic
// (~60 warp-instrs per 128-point chunk vs ~108 scalar).
//
// Chunk = 128 points (1536B x + 1536B y). 8 chunks per batch.
// 3-slot ring per warp, 2 chunks in flight. No __syncthreads.

#define SLOT_BYTES   3072
#define WARP_SMEM    (3 * SLOT_BYTES)   // 9216B ring per warp
#define CTA_SMEM     (8 * WARP_SMEM)    // 73728B per CTA (8 warps)

__device__ __forceinline__ void cp_async16(uint32_t saddr, const void* gaddr) {
    asm volatile("cp.async.cg.shared.global [%0], [%1], 16;\n"
                 :: "r"(saddr), "l"(gaddr));
}
__device__ __forceinline__ void cp_commit() {
    asm volatile("cp.async.commit_group;\n");
}
template <int N>
__device__ __forceinline__ void cp_wait() {
    asm volatile("cp.async.wait_group %0;\n" :: "n"(N));
}

// ---- packed f32x2 helpers ----
__device__ __forceinline__ uint64_t pk2(float lo, float hi) {
    uint64_t r; asm("mov.b64 %0, {%1, %2};" : "=l"(r) : "f"(lo), "f"(hi)); return r;
}
__device__ __forceinline__ void upk2(uint64_t v, float& lo, float& hi) {
    asm("mov.b64 {%0, %1}, %2;" : "=f"(lo), "=f"(hi) : "l"(v));
}
__device__ __forceinline__ uint64_t add2(uint64_t a, uint64_t b) {
    uint64_t r; asm("add.rn.f32x2 %0, %1, %2;" : "=l"(r) : "l"(a), "l"(b)); return r;
}
__device__ __forceinline__ uint64_t fma2(uint64_t a, uint64_t b, uint64_t c) {
    uint64_t r; asm("fma.rn.f32x2 %0, %1, %2, %3;" : "=l"(r) : "l"(a), "l"(b), "l"(c)); return r;
}

__global__ __launch_bounds__(256, 3)
void align9dof_kernel(const float* __restrict__ x,
                      const float* __restrict__ mu_x,
                      const float* __restrict__ y,
                      const float* __restrict__ mu_y,
                      float* __restrict__ out,
                      int B)
{
    extern __shared__ char smem_dyn[];

    const int warp = threadIdx.x >> 5;
    const int lane = threadIdx.x & 31;
    const int gw   = blockIdx.x * 8 + warp;   // global warp id
    const int ws   = gridDim.x * 8;           // warp stride
    if (gw >= B) return;

    const int nb   = (B - 1 - gw) / ws + 1;   // batches this warp owns
    const int qtot = nb * 8;                  // chunks in this warp's stream

    char* wbase = smem_dyn + warp * WARP_SMEM;
    const uint32_t sbase = (uint32_t)__cvta_generic_to_shared(wbase);

    auto issue_chunk = [&](int q) {
        const size_t bq = (size_t)gw + (size_t)(q >> 3) * ws;
        const char* gx = (const char*)(x + bq * 3072) + (q & 7) * 1536 + lane * 16;
        const char* gy = (const char*)(y + bq * 3072) + (q & 7) * 1536 + lane * 16;
        const uint32_t s = sbase + (q % 3) * SLOT_BYTES + lane * 16;
#pragma unroll
        for (int k = 0; k < 3; k++) {
            cp_async16(s + k * 512,        gx + k * 512);
            cp_async16(s + 1536 + k * 512, gy + k * 512);
        }
        cp_commit();
    };

    issue_chunk(0);
    issue_chunk(1);

    // Packed negated means (set per batch)
    uint64_t nmx0 = 0, nmx1 = 0, nmx2 = 0, nmy0 = 0, nmy1 = 0, nmy2 = 0;
    float mx0 = 0.f, mx1 = 0.f, mx2 = 0.f, my0 = 0.f, my1 = 0.f, my2 = 0.f;

    uint64_t acc[11];  // packed f32x2: c00..c22, sxx, syy
#pragma unroll
    for (int i = 0; i < 11; i++) acc[i] = 0;

    for (int q = 0; q < qtot; q++) {
        if (q + 2 < qtot) issue_chunk(q + 2);

        const int remaining = qtot - 1 - q;
        if (remaining >= 2)      cp_wait<2>();
        else if (remaining == 1) cp_wait<1>();
        else                     cp_wait<0>();
        __syncwarp();

        const int bcur = gw + (q >> 3) * ws;
        if ((q & 7) == 0) {
            mx0 = mu_x[bcur * 3 + 0]; mx1 = mu_x[bcur * 3 + 1]; mx2 = mu_x[bcur * 3 + 2];
            my0 = mu_y[bcur * 3 + 0]; my1 = mu_y[bcur * 3 + 1]; my2 = mu_y[bcur * 3 + 2];
            nmx0 = pk2(-mx0, -mx0); nmx1 = pk2(-mx1, -mx1); nmx2 = pk2(-mx2, -mx2);
            nmy0 = pk2(-my0, -my0); nmy1 = pk2(-my1, -my1); nmy2 = pk2(-my2, -my2);
        }

        // LDS.128 readback: 3 float4 per array per lane = 4 points
        const float4* s4x = (const float4*)(wbase + (q % 3) * SLOT_BYTES);
        const float4* s4y = s4x + 96;  // +1536B

        const float4 xa = s4x[3 * lane + 0];
        const float4 xm = s4x[3 * lane + 1];
        const float4 xc = s4x[3 * lane + 2];
        const float4 ya = s4y[3 * lane + 0];
        const float4 ym = s4y[3 * lane + 1];
        const float4 yc = s4y[3 * lane + 2];

        // Pair A = points (p0,p1), Pair B = points (p2,p3)
        uint64_t uA0 = add2(pk2(xa.x, xa.w), nmx0);
        uint64_t uA1 = add2(pk2(xa.y, xm.x), nmx1);
        uint64_t uA2 = add2(pk2(xa.z, xm.y), nmx2);
        uint64_t uB0 = add2(pk2(xm.z, xc.y), nmx0);
        uint64_t uB1 = add2(pk2(xm.w, xc.z), nmx1);
        uint64_t uB2 = add2(pk2(xc.x, xc.w), nmx2);

        uint64_t wA0 = add2(pk2(ya.x, ya.w), nmy0);
        uint64_t wA1 = add2(pk2(ya.y, ym.x), nmy1);
        uint64_t wA2 = add2(pk2(ya.z, ym.y), nmy2);
        uint64_t wB0 = add2(pk2(ym.z, yc.y), nmy0);
        uint64_t wB1 = add2(pk2(ym.w, yc.z), nmy1);
        uint64_t wB2 = add2(pk2(yc.x, yc.w), nmy2);

        acc[0] = fma2(uA0, wA0, acc[0]); acc[0] = fma2(uB0, wB0, acc[0]);
        acc[1] = fma2(uA0, wA1, acc[1]); acc[1] = fma2(uB0, wB1, acc[1]);
        acc[2] = fma2(uA0, wA2, acc[2]); acc[2] = fma2(uB0, wB2, acc[2]);
        acc[3] = fma2(uA1, wA0, acc[3]); acc[3] = fma2(uB1, wB0, acc[3]);
        acc[4] = fma2(uA1, wA1, acc[4]); acc[4] = fma2(uB1, wB1, acc[4]);
        acc[5] = fma2(uA1, wA2, acc[5]); acc[5] = fma2(uB1, wB2, acc[5]);
        acc[6] = fma2(uA2, wA0, acc[6]); acc[6] = fma2(uB2, wB0, acc[6]);
        acc[7] = fma2(uA2, wA1, acc[7]); acc[7] = fma2(uB2, wB1, acc[7]);
        acc[8] = fma2(uA2, wA2, acc[8]); acc[8] = fma2(uB2, wB2, acc[8]);

        acc[9]  = fma2(uA0, uA0, acc[9]);  acc[9]  = fma2(uA1, uA1, acc[9]);
        acc[9]  = fma2(uA2, uA2, acc[9]);  acc[9]  = fma2(uB0, uB0, acc[9]);
        acc[9]  = fma2(uB1, uB1, acc[9]);  acc[9]  = fma2(uB2, uB2, acc[9]);
        acc[10] = fma2(wA0, wA0, acc[10]); acc[10] = fma2(wA1, wA1, acc[10]);
        acc[10] = fma2(wA2, wA2, acc[10]); acc[10] = fma2(wB0, wB0, acc[10]);
        acc[10] = fma2(wB1, wB1, acc[10]); acc[10] = fma2(wB2, wB2, acc[10]);

        __syncwarp();  // all lanes done reading slot before refill

        if ((q & 7) == 7) {
            // ---- Batch epilogue (next batch's loads already in flight) ----
            float v[11];
#pragma unroll
            for (int i = 0; i < 11; i++) {
                float lo, hi;
                upk2(acc[i], lo, hi);
                v[i] = lo + hi;
                acc[i] = 0;
            }

#pragma unroll
            for (int off = 16; off > 0; off >>= 1) {
#pragma unroll
                for (int i = 0; i < 11; i++)
                    v[i] += __shfl_xor_sync(0xFFFFFFFFu, v[i], off);
            }

            float fro2 = 0.0f;
#pragma unroll
            for (int i = 0; i < 9; i++) fro2 = fmaf(v[i], v[i], fro2);
            const float invf = rsqrtf(fmaxf(fro2, 1e-30f));

            float X[9];
#pragma unroll
            for (int i = 0; i < 9; i++) X[i] = v[i] * invf;

#pragma unroll
            for (int it = 0; it < 8; it++) {
                float C[9];  // cofactors: X^{-T} = C / det
                C[0] = X[4] * X[8] - X[5] * X[7];
                C[1] = X[5] * X[6] - X[3] * X[8];
                C[2] = X[3] * X[7] - X[4] * X[6];
                C[3] = X[2] * X[7] - X[1] * X[8];
                C[4] = X[0] * X[8] - X[2] * X[6];
                C[5] = X[1] * X[6] - X[0] * X[7];
                C[6] = X[1] * X[5] - X[2] * X[4];
                C[7] = X[2] * X[3] - X[0] * X[5];
                C[8] = X[0] * X[4] - X[1] * X[3];
                float det = X[0] * C[0] + X[1] * C[1] + X[2] * C[2];
                float ad  = fmaxf(fabsf(det), 1e-30f);
                float eta = rcbrtf(ad);            // |det|^{-1/3}
                float k1  = 0.5f * eta;
                float k2  = 0.5f / (eta * det);    // keeps det's sign
#pragma unroll
                for (int i = 0; i < 9; i++) X[i] = k1 * X[i] + k2 * C[i];
            }

            const float t0 = my0 - (X[0] * mx0 + X[1] * mx1 + X[2] * mx2);
            const float t1 = my1 - (X[3] * mx0 + X[4] * mx1 + X[5] * mx2);
            const float t2 = my2 - (X[6] * mx0 + X[7] * mx1 + X[8] * mx2);
            const float sf = sqrtf(v[10]) / (sqrtf(v[9]) + 1e-6f);

            if (lane < 9) {
                float r = (lane == 0) ? X[0] :
                          (lane == 1) ? X[1] :
                          (lane == 2) ? X[2] :
                          (lane == 3) ? X[3] :
                          (lane == 4) ? X[4] :
                          (lane == 5) ? X[5] :
                          (lane == 6) ? X[6] :
                          (lane == 7) ? X[7] : X[8];
                out[(size_t)bcur * 9 + lane] = r;
            }
            if (lane < 3) {
                float tv = (lane == 0) ? t0 : (lane == 1) ? t1 : t2;
                out[(size_t)B * 9 + (size_t)bcur * 3 + lane] = tv;
            }
            if (lane == 0) {
                out[(size_t)B * 12 + bcur] = sf;
            }
        }
    }
}

extern "C" void kernel_launch(void* const* d_in, const int* in_sizes, int n_in,
                              void* d_out, int out_size)
{
    const float* x    = (const float*)d_in[0];
    const float* mu_x = (const float*)d_in[1];
    const float* y    = (const float*)d_in[2];
    const float* mu_y = (const float*)d_in[3];
    float* out        = (float*)d_out;

    const int B = in_sizes[1] / 3;  // mu_x is [B,3]

    cudaFuncSetAttribute(align9dof_kernel,
                         cudaFuncAttributeMaxDynamicSharedMemorySize, CTA_SMEM);

    int grid = 148 * 3;                       // persistent: 3 CTAs per SM
    const int maxg = (B + 7) / 8;
    if (grid > maxg) grid = maxg;

    align9dof_kernel<<<grid, 256, CTA_SMEM>>>(x, mu_x, y, mu_y, out, B);
}